// round 1
// baseline (speedup 1.0000x reference)
#include <cuda_runtime.h>
#include <cstdint>

// x: [N=64, C=512, H=56, W=56] fp32. 2:4 structured sparsity along C:
// within each contiguous group of 4 channels (same n,h,w), zero the 2
// smallest-|x| entries (ties: lower channel index dropped first).
//
// Layout facts: HW = 56*56 = 3136 floats (divisible by 4), channel stride
// = 3136 floats. Each thread processes one group of 4 channels at 4
// consecutive hw positions via float4: 4 strided float4 loads, mask,
// 4 float4 stores. Fully coalesced; memory-bound streaming.

static constexpr int N_DIM  = 64;
static constexpr int C_DIM  = 512;
static constexpr int HW     = 56 * 56;          // 3136
static constexpr int HW4    = HW / 4;           // 784 float4 per plane
static constexpr int GROUPS = C_DIM / 4;        // 128
static constexpr long long TOTAL_T = (long long)N_DIM * GROUPS * HW4; // 6,422,528

// keep element i iff at least 2 of the other 3 are "strictly smaller"
// under (|a_j| < |a_i|) || (|a_j| == |a_i| && j < i)  -- matches jax top_k
// dropping the 2 smallest with lower-index tie preference.
__device__ __forceinline__ void mask4(float& x0, float& x1, float& x2, float& x3) {
    float a0 = fabsf(x0), a1 = fabsf(x1), a2 = fabsf(x2), a3 = fabsf(x3);
    // rank_i = number of j with less(j, i)
    int r0 = 0, r1 = 0, r2 = 0, r3 = 0;
    // pair (0,1)
    if (a0 < a1 || a0 == a1) r1++; else r0++;   // j=0 < i=1: tie -> 0 before 1
    // careful: less(0,1) = (a0<a1)||(a0==a1 && 0<1) = a0<=a1 ; less(1,0)= a1<a0
    // pair (0,2)
    if (a0 <= a2) r2++; else r0++;
    // pair (0,3)
    if (a0 <= a3) r3++; else r0++;
    // pair (1,2)
    if (a1 <= a2) r2++; else r1++;
    // pair (1,3)
    if (a1 <= a3) r3++; else r1++;
    // pair (2,3)
    if (a2 <= a3) r3++; else r2++;
    x0 = (r0 >= 2) ? x0 : 0.0f;
    x1 = (r1 >= 2) ? x1 : 0.0f;
    x2 = (r2 >= 2) ? x2 : 0.0f;
    x3 = (r3 >= 2) ? x3 : 0.0f;
}

__global__ void __launch_bounds__(256)
sparsity24_kernel(const float4* __restrict__ x4, float4* __restrict__ o4) {
    long long t = (long long)blockIdx.x * blockDim.x + threadIdx.x;
    if (t >= TOTAL_T) return;

    // decode: t -> (n, g, hw4)
    int hw4 = (int)(t % HW4);
    long long ng = t / HW4;
    int g = (int)(ng % GROUPS);
    long long n = ng / GROUPS;

    // base float4 index of channel c = g*4 within this n
    long long base = (n * C_DIM + (long long)g * 4) * HW4 + hw4;

    float4 v0 = x4[base];
    float4 v1 = x4[base + HW4];
    float4 v2 = x4[base + 2 * HW4];
    float4 v3 = x4[base + 3 * HW4];

    // lane .x
    mask4(v0.x, v1.x, v2.x, v3.x);
    mask4(v0.y, v1.y, v2.y, v3.y);
    mask4(v0.z, v1.z, v2.z, v3.z);
    mask4(v0.w, v1.w, v2.w, v3.w);

    o4[base]           = v0;
    o4[base + HW4]     = v1;
    o4[base + 2 * HW4] = v2;
    o4[base + 3 * HW4] = v3;
}

extern "C" void kernel_launch(void* const* d_in, const int* in_sizes, int n_in,
                              void* d_out, int out_size) {
    const float4* x4 = (const float4*)d_in[0];
    float4* o4 = (float4*)d_out;
    int threads = 256;
    long long blocks = (TOTAL_T + threads - 1) / threads;
    sparsity24_kernel<<<(unsigned)blocks, threads>>>(x4, o4);
}